// round 10
// baseline (speedup 1.0000x reference)
#include <cuda_runtime.h>
#include <cuda_fp16.h>
#include <stdint.h>

#define N_NODES 100000
#define BATCH   50000
#define K       10
#define DIM     128

// fp16 feature table: 25.6 MB (L2-resident hot set; verified by gather DRAM
// traffic == output-write only).
__device__ __half g_tab16[N_NODES * DIM];

// ---------------------------------------------------------------------------
// Pass 1: fp32 -> fp16. One thread = 32B of table (4 LDG.128 + 2 STG.128).
// ---------------------------------------------------------------------------
__global__ __launch_bounds__(256) void convert_kernel(const float4* __restrict__ feat)
{
    const int i = blockIdx.x * blockDim.x + threadIdx.x;
    const int n32 = N_NODES * DIM / 16;                 // 800k
    if (i >= n32) return;

    float4 a = __ldg(&feat[i * 4 + 0]);
    float4 b = __ldg(&feat[i * 4 + 1]);
    float4 c = __ldg(&feat[i * 4 + 2]);
    float4 d = __ldg(&feat[i * 4 + 3]);

    __half2 h0 = __float22half2_rn(make_float2(a.x, a.y));
    __half2 h1 = __float22half2_rn(make_float2(a.z, a.w));
    __half2 h2 = __float22half2_rn(make_float2(b.x, b.y));
    __half2 h3 = __float22half2_rn(make_float2(b.z, b.w));
    __half2 h4 = __float22half2_rn(make_float2(c.x, c.y));
    __half2 h5 = __float22half2_rn(make_float2(c.z, c.w));
    __half2 h6 = __float22half2_rn(make_float2(d.x, d.y));
    __half2 h7 = __float22half2_rn(make_float2(d.z, d.w));

    uint4 p0, p1;
    p0.x = *reinterpret_cast<unsigned*>(&h0);
    p0.y = *reinterpret_cast<unsigned*>(&h1);
    p0.z = *reinterpret_cast<unsigned*>(&h2);
    p0.w = *reinterpret_cast<unsigned*>(&h3);
    p1.x = *reinterpret_cast<unsigned*>(&h4);
    p1.y = *reinterpret_cast<unsigned*>(&h5);
    p1.z = *reinterpret_cast<unsigned*>(&h6);
    p1.w = *reinterpret_cast<unsigned*>(&h7);

    uint4* dst = reinterpret_cast<uint4*>(g_tab16);
    dst[i * 2 + 0] = p0;
    dst[i * 2 + 1] = p1;
}

static __device__ __forceinline__ __half2 H2(const unsigned& u)
{
    return *reinterpret_cast<const __half2*>(&u);
}

// ---------------------------------------------------------------------------
// Pass 2: gather-mean with cp.async staging.
// Half-warp per row (16 lanes x uint4 = 256B fp16 row), 2 rows per warp.
// Each thread issues 11 cp.async.cg 16B copies (gmem->smem). cp.async has NO
// destination register, so ptxas CANNOT serialize it for register reuse —
// hardware-guaranteed MLP=11, unlike every register-staged variant (all of
// which ptxas collapsed to ~30 regs / serialized loads).
// ---------------------------------------------------------------------------
__global__ __launch_bounds__(256) void gather_kernel(
    const int* __restrict__ nodes,
    const int* __restrict__ neighbours,
    float4* __restrict__ out)
{
    // smem staging: 8 warps * 2 rows * 11 k * 16 lanes * 16B = 45056 B
    __shared__ uint4 stage[8 * 2 * (K + 1) * 16];

    const int wib   = threadIdx.x >> 5;               // warp in block (0..7)
    const int gwarp = blockIdx.x * 8 + wib;
    const int lane  = threadIdx.x & 31;
    const int half  = lane >> 4;
    const int hl    = lane & 15;
    const int row   = gwarp * 2 + half;
    if (row >= BATCH) return;

    // Lanes 0..10 of each half-warp fetch the 11 ids; broadcast via shfl
    // (coalesced 2-sector index read instead of 11 scalar loads).
    int my = 0;
    if (hl == 0)      my = __ldg(&nodes[row]);
    else if (hl <= K) my = __ldg(&neighbours[row * K + (hl - 1)]);

    int idx[K + 1];
#pragma unroll
    for (int k = 0; k < K + 1; k++)
        idx[k] = __shfl_sync(0xFFFFFFFFu, my, half * 16 + k);

    const uint4* tab = reinterpret_cast<const uint4*>(g_tab16);

    // This thread's staging slots: ((wib*2+half)*(K+1) + k)*16 + hl
    const int slot_base = (wib * 2 + half) * (K + 1) * 16 + hl;

    unsigned smem_addr_base;
    {
        uint4* p = &stage[slot_base];
        smem_addr_base = (unsigned)__cvta_generic_to_shared(p);
    }

    // 11 cp.async.cg (L1-bypass) 16B copies — all in flight simultaneously.
#pragma unroll
    for (int k = 0; k < K + 1; k++) {
        const uint4* src = &tab[idx[k] * 16 + hl];
        unsigned dst = smem_addr_base + (unsigned)(k * 16 * sizeof(uint4));
        asm volatile("cp.async.cg.shared.global [%0], [%1], 16;\n"
                     :: "r"(dst), "l"(src));
    }
    asm volatile("cp.async.commit_group;\n");
    asm volatile("cp.async.wait_group 0;\n");
    __syncwarp();

    // Reduce from smem: 4 half2 accumulators (this thread's 16B of the row).
    uint4 v0 = stage[slot_base];
    __half2 a0 = H2(v0.x), a1 = H2(v0.y), a2 = H2(v0.z), a3 = H2(v0.w);
#pragma unroll
    for (int k = 1; k < K + 1; k++) {
        uint4 v = stage[slot_base + k * 16];
        a0 = __hadd2(a0, H2(v.x));
        a1 = __hadd2(a1, H2(v.y));
        a2 = __hadd2(a2, H2(v.z));
        a3 = __hadd2(a3, H2(v.w));
    }

    const float s = 1.0f / (float)(K + 1);
    float2 f0 = __half22float2(a0);
    float2 f1 = __half22float2(a1);
    float2 f2 = __half22float2(a2);
    float2 f3 = __half22float2(a3);

    float4 o0 = make_float4(f0.x * s, f0.y * s, f1.x * s, f1.y * s);
    float4 o1 = make_float4(f2.x * s, f2.y * s, f3.x * s, f3.y * s);

    // fp32 output row = 32 float4; this thread owns slots 2*hl, 2*hl+1.
    __stcs(&out[row * 32 + hl * 2 + 0], o0);
    __stcs(&out[row * 32 + hl * 2 + 1], o1);
}

extern "C" void kernel_launch(void* const* d_in, const int* in_sizes, int n_in,
                              void* d_out, int out_size)
{
    const int*    nodes      = (const int*)d_in[0];
    const int*    neighbours = (const int*)d_in[1];
    const float4* features   = (const float4*)d_in[2];
    float4*       out        = (float4*)d_out;

    const int n32 = N_NODES * DIM / 16;
    convert_kernel<<<(n32 + 255) / 256, 256>>>(features);

    // 2 rows per warp, 8 warps per block -> 16 rows/block.
    const int blocks = (BATCH + 15) / 16;
    gather_kernel<<<blocks, 256>>>(nodes, neighbours, out);
}

// round 11
// speedup vs baseline: 1.0808x; 1.0808x over previous
#include <cuda_runtime.h>
#include <cuda_fp16.h>
#include <stdint.h>

#define N_NODES 100000
#define BATCH   50000
#define K       10
#define DIM     128

// Split fp16 table: lo = first 128B of each row, hi = second 128B.
// The two halves of one logical row live 12.8MB apart, so their cache lines
// hash to INDEPENDENT LTS partitions (a packed 256B row's two lines differ
// only in transparent bit 7 -> same partition -> per-row burst serialization).
__device__ __half g_lo[N_NODES * 64];   // 12.8 MB
__device__ __half g_hi[N_NODES * 64];   // 12.8 MB

// ---------------------------------------------------------------------------
// Pass 1: fp32 -> split fp16 tables. One thread = 32B of fp16 output
// (16 floats in, 4 LDG.128 + 1 STG.128). Chunk j of 8 within a row:
// j<4 -> lo half, j>=4 -> hi half.
// ---------------------------------------------------------------------------
__global__ __launch_bounds__(256) void convert_kernel(const float4* __restrict__ feat)
{
    const int g = blockIdx.x * blockDim.x + threadIdx.x;   // one 16B fp16 chunk
    const int nchunks = N_NODES * 8;                       // 8 chunks per row
    if (g >= nchunks) return;

    const int row = g >> 3;
    const int j   = g & 7;

    // 16B of fp16 = 8 halfs = 8 floats = 2 float4 from the source.
    const float4* src = feat + (size_t)row * 32 + j * 4;
    float4 a = __ldg(&src[0]);
    float4 b = __ldg(&src[1]);
    float4 c = __ldg(&src[2]);
    float4 d = __ldg(&src[3]);

    __half2 h0 = __float22half2_rn(make_float2(a.x, a.y));
    __half2 h1 = __float22half2_rn(make_float2(a.z, a.w));
    __half2 h2 = __float22half2_rn(make_float2(b.x, b.y));
    __half2 h3 = __float22half2_rn(make_float2(b.z, b.w));
    __half2 h4 = __float22half2_rn(make_float2(c.x, c.y));
    __half2 h5 = __float22half2_rn(make_float2(c.z, c.w));
    __half2 h6 = __float22half2_rn(make_float2(d.x, d.y));
    __half2 h7 = __float22half2_rn(make_float2(d.z, d.w));

    uint4 p0, p1;
    p0.x = *reinterpret_cast<unsigned*>(&h0);
    p0.y = *reinterpret_cast<unsigned*>(&h1);
    p0.z = *reinterpret_cast<unsigned*>(&h2);
    p0.w = *reinterpret_cast<unsigned*>(&h3);
    p1.x = *reinterpret_cast<unsigned*>(&h4);
    p1.y = *reinterpret_cast<unsigned*>(&h5);
    p1.z = *reinterpret_cast<unsigned*>(&h6);
    p1.w = *reinterpret_cast<unsigned*>(&h7);

    // j covers 32B = 2 uint4. Half-table row = 128B = 8 uint4.
    __half* base = (j < 4) ? g_lo : g_hi;
    const int jj = j & 3;
    uint4* dst = reinterpret_cast<uint4*>(base) + (size_t)row * 8 + jj * 2;
    dst[0] = p0;
    dst[1] = p1;
}

static __device__ __forceinline__ __half2 H2(const unsigned& u)
{
    return *reinterpret_cast<const __half2*>(&u);
}

// ---------------------------------------------------------------------------
// Pass 2: gather-mean. One warp per row; lane owns 4 columns (uint2 = 8B).
// Lanes 0-15 read from g_lo, lanes 16-31 from g_hi -> each warp-load now
// touches 2 cache lines on 2 INDEPENDENT LTS partitions (vs 1 partition for
// a packed 256B row). Same sector count, same instruction count.
// ---------------------------------------------------------------------------
__global__ __launch_bounds__(256) void gather_kernel(
    const int* __restrict__ nodes,
    const int* __restrict__ neighbours,
    float4* __restrict__ out)
{
    const int warp = (blockIdx.x * blockDim.x + threadIdx.x) >> 5;
    const int lane = threadIdx.x & 31;
    if (warp >= BATCH) return;

    int idx[K + 1];
    idx[0] = __ldg(&nodes[warp]);
#pragma unroll
    for (int k = 0; k < K; k++) idx[k + 1] = __ldg(&neighbours[warp * K + k]);

    // Lane's base pointer: lo-half for lanes 0-15, hi-half for lanes 16-31.
    // Half-table row = 128B = 16 uint2; lane slot = lane & 15.
    const uint2* tab = reinterpret_cast<const uint2*>((lane < 16) ? g_lo : g_hi);
    const int slot = lane & 15;

    uint2 v[K + 1];
#pragma unroll
    for (int k = 0; k < K + 1; k++)
        v[k] = __ldg(&tab[idx[k] * 16 + slot]);

    __half2 acc01 = H2(v[0].x);
    __half2 acc23 = H2(v[0].y);
#pragma unroll
    for (int k = 1; k < K + 1; k++) {
        acc01 = __hadd2(acc01, H2(v[k].x));
        acc23 = __hadd2(acc23, H2(v[k].y));
    }

    const float s = 1.0f / (float)(K + 1);
    float2 f01 = __half22float2(acc01);
    float2 f23 = __half22float2(acc23);

    // Lane owns output columns: lo lanes -> cols [4*slot), hi lanes -> +64.
    // out row = 32 float4; lo lane slot s -> float4 index s (cols 4s..4s+3)?
    // Careful: lo half holds cols 0..63 (16 uint2 = 64 halfs), hi holds 64..127.
    // Lane's 4 columns = (lane<16 ? 0 : 64) + 4*slot .. +3  -> float4 index
    // = (lane<16 ? 0 : 16) + slot.
    const int f4idx = ((lane < 16) ? 0 : 16) + slot;

    float4 o;
    o.x = f01.x * s;
    o.y = f01.y * s;
    o.z = f23.x * s;
    o.w = f23.y * s;
    __stcs(&out[warp * 32 + f4idx], o);
}

extern "C" void kernel_launch(void* const* d_in, const int* in_sizes, int n_in,
                              void* d_out, int out_size)
{
    const int*    nodes      = (const int*)d_in[0];
    const int*    neighbours = (const int*)d_in[1];
    const float4* features   = (const float4*)d_in[2];
    float4*       out        = (float4*)d_out;

    const int nchunks = N_NODES * 8;
    convert_kernel<<<(nchunks + 255) / 256, 256>>>(features);

    const int warps_per_block = 256 / 32;
    const int blocks = (BATCH + warps_per_block - 1) / warps_per_block;
    gather_kernel<<<blocks, 256>>>(nodes, neighbours, out);
}